// round 15
// baseline (speedup 1.0000x reference)
#include <cuda_runtime.h>
#include <cuda_bf16.h>
#include <math.h>
#include <stdint.h>

#define B_  2
#define S_  2048
#define D_  2048
#define H_  16
#define HD_ 128
#define M_  (B_*S_)      // 4096
#define F_  (HD_/2)      // 64

// ---------------- scratch (alloc-free rule: __device__ globals) ----------------
__device__ float g_cos[S_*F_];
__device__ float g_sin[S_*F_];

__device__ __nv_bfloat16 g_qhi[B_*H_*S_*HD_];
__device__ __nv_bfloat16 g_qlo[B_*H_*S_*HD_];
__device__ __nv_bfloat16 g_khi[B_*H_*S_*HD_];
__device__ __nv_bfloat16 g_klo[B_*H_*S_*HD_];
__device__ __nv_bfloat16 g_vhi[B_*H_*S_*HD_];
__device__ __nv_bfloat16 g_vlo[B_*H_*S_*HD_];

__device__ __nv_bfloat16 g_xhi[M_*D_];   // x split; reused as attn-out split
__device__ __nv_bfloat16 g_xlo[M_*D_];
__device__ __nv_bfloat16 g_whi[4*D_*D_];
__device__ __nv_bfloat16 g_wlo[4*D_*D_];

// ---------------- PTX helpers (plain sm_100 target: no tcgen05) ----------------
__device__ __forceinline__ uint32_t smem_u32(const void* p) {
    uint32_t a;
    asm("{ .reg .u64 t; cvta.to.shared.u64 t, %1; cvt.u32.u64 %0, t; }" : "=r"(a) : "l"(p));
    return a;
}
__device__ __forceinline__ void cp16(uint32_t s, const void* g) {
    asm volatile("cp.async.cg.shared.global [%0], [%1], 16;" :: "r"(s), "l"(g));
}
#define CP_COMMIT() asm volatile("cp.async.commit_group;")

__device__ __forceinline__ void ldsm4(uint32_t* r, uint32_t addr) {
    asm volatile("ldmatrix.sync.aligned.m8n8.x4.shared.b16 {%0,%1,%2,%3}, [%4];"
        : "=r"(r[0]), "=r"(r[1]), "=r"(r[2]), "=r"(r[3]) : "r"(addr));
}
__device__ __forceinline__ void ldsm4t(uint32_t* r, uint32_t addr) {
    asm volatile("ldmatrix.sync.aligned.m8n8.x4.trans.shared.b16 {%0,%1,%2,%3}, [%4];"
        : "=r"(r[0]), "=r"(r[1]), "=r"(r[2]), "=r"(r[3]) : "r"(addr));
}
__device__ __forceinline__ void mma16816(float* d, const uint32_t* a, uint32_t b0, uint32_t b1) {
    asm volatile(
        "mma.sync.aligned.m16n8k16.row.col.f32.bf16.bf16.f32 "
        "{%0,%1,%2,%3}, {%4,%5,%6,%7}, {%8,%9}, {%0,%1,%2,%3};"
        : "+f"(d[0]), "+f"(d[1]), "+f"(d[2]), "+f"(d[3])
        : "r"(a[0]), "r"(a[1]), "r"(a[2]), "r"(a[3]), "r"(b0), "r"(b1));
}
__device__ __forceinline__ uint32_t pack_bf16x2(float a, float b) {
    __nv_bfloat162 t = __halves2bfloat162(__float2bfloat16(a), __float2bfloat16(b));
    return *reinterpret_cast<uint32_t*>(&t);
}
// SW64-style bank swizzle for 64B rows; preserves 16B granularity
__device__ __forceinline__ uint32_t swz64(uint32_t x) { return x ^ ((x >> 3) & 0x30); }
// swizzle for 256B rows: row bits [8:10] -> 16B-column bits [4:6]
__device__ __forceinline__ uint32_t swz256(uint32_t x) { return x ^ ((x >> 4) & 0x70); }

// ---------------- RoPE table ----------------
__global__ void rope_table_kernel() {
    int idx = blockIdx.x * blockDim.x + threadIdx.x;
    if (idx >= S_ * F_) return;
    int s = idx >> 6;
    int i = idx & 63;
    double invf = pow(10000.0, -(double)i / 64.0);
    double f = (double)s * invf;
    double sn, cs;
    sincos(f, &sn, &cs);
    g_cos[idx] = (float)cs;
    g_sin[idx] = (float)sn;
}

// ---------------- fp32 -> bf16 hi/lo splits ----------------
// y0=0, ny=2: x halves.  y0=2, ny=4: Wq,Wk,Wv,Wo.
__global__ void conv_fused(const float* __restrict__ x,
                           const float* __restrict__ Wq, const float* __restrict__ Wk,
                           const float* __restrict__ Wv, const float* __restrict__ Wo,
                           __nv_bfloat16* __restrict__ xhi, __nv_bfloat16* __restrict__ xlo,
                           __nv_bfloat16* __restrict__ whi, __nv_bfloat16* __restrict__ wlo,
                           int y0)
{
    const int y = blockIdx.y + y0;
    const int i = blockIdx.x * blockDim.x + threadIdx.x;
    const float* in;
    __nv_bfloat16 *hi, *lo;
    size_t off4;
    const size_t SEG = (size_t)D_ * D_ / 4;
    if (y < 2) {
        in = x + (size_t)y * SEG * 4;
        hi = xhi; lo = xlo;
        off4 = (size_t)y * SEG + i;
    } else {
        const float* ws[4] = {Wq, Wk, Wv, Wo};
        in = ws[y - 2];
        hi = whi; lo = wlo;
        off4 = (size_t)(y - 2) * SEG + i;
    }
    float4 v = ((const float4*)in)[i];
    float xs[4] = {v.x, v.y, v.z, v.w};
    __nv_bfloat16 h[4], l[4];
    #pragma unroll
    for (int j = 0; j < 4; j++) {
        h[j] = __float2bfloat16(xs[j]);
        l[j] = __float2bfloat16(xs[j] - __bfloat162float(h[j]));
    }
    __nv_bfloat162* hp = (__nv_bfloat162*)hi;
    __nv_bfloat162* lp = (__nv_bfloat162*)lo;
    hp[2*off4]   = __halves2bfloat162(h[0], h[1]);
    hp[2*off4+1] = __halves2bfloat162(h[2], h[3]);
    lp[2*off4]   = __halves2bfloat162(l[0], l[1]);
    lp[2*off4+1] = __halves2bfloat162(l[2], l[3]);
}

// ---------------- mma.sync bf16 GEMM machinery (unchanged from round 14) ----------------
#define KC 32
#define TILE_B (128*64)              // 8192
#define STAGE_B (4*TILE_B)           // 32768
#define GT_SMEM (3*STAGE_B)          // 98304

struct GemmCore {
    uint32_t sb;
    int tid, lane, wid, wm, wn, m0, n0;
    const __nv_bfloat16 *Ahi, *Alo, *Bhi, *Blo;

    __device__ __forceinline__ void init(uint32_t sb_, int bx, int by) {
        sb = sb_;
        tid = threadIdx.x;
        lane = tid & 31;
        wid = tid >> 5;              // 0..3
        wm = (wid >> 1) * 64;
        wn = (wid & 1) * 64;
        m0 = by * 128;
        n0 = bx * 128;
    }

    __device__ __forceinline__ void load_stage(int stg, int k0) {
        if (k0 < 2048) {
            uint32_t base = sb + stg * STAGE_B;
            #pragma unroll
            for (int t = 0; t < 4; t++) {
                int idx = t * 128 + tid;
                int row = idx >> 2, seg = idx & 3;
                uint32_t so = swz64(row * 64 + seg * 16);
                size_t goA = (size_t)(m0 + row) * D_ + k0 + seg * 8;
                size_t goB = (size_t)(n0 + row) * D_ + k0 + seg * 8;
                cp16(base + 0*TILE_B + so, Ahi + goA);
                cp16(base + 1*TILE_B + so, Alo + goA);
                cp16(base + 2*TILE_B + so, Bhi + goB);
                cp16(base + 3*TILE_B + so, Blo + goB);
            }
        }
        CP_COMMIT();   // empty commit past the tail keeps group counting uniform
    }

    // acc[mi][ni][e]: mi 0..3 (m16 rows), ni 0..7 (n8 cols)
    __device__ __forceinline__ void run(float acc[4][8][4]) {
        #pragma unroll
        for (int mi = 0; mi < 4; mi++)
            #pragma unroll
            for (int ni = 0; ni < 8; ni++)
                #pragma unroll
                for (int e = 0; e < 4; e++) acc[mi][ni][e] = 0.f;

        load_stage(0, 0);
        load_stage(1, KC);
        const int NCH = 2048 / KC;
        const int lrow = lane & 15;
        const int lk   = (lane >> 4) * 8;

        int stg = 0;
        for (int c = 0; c < NCH; c++) {
            asm volatile("cp.async.wait_group 1;" ::: "memory");
            __syncthreads();
            int nst = stg + 2; if (nst >= 3) nst -= 3;
            load_stage(nst, (c + 2) * KC);

            const uint32_t st = sb + stg * STAGE_B;
            const uint32_t aAh = st, aAl = st + TILE_B, aBh = st + 2*TILE_B, aBl = st + 3*TILE_B;

            #pragma unroll
            for (int kk = 0; kk < 2; kk++) {
                const int kb = (kk * 16 + lk) * 2;
                uint32_t ah[4][4], al[4][4];
                #pragma unroll
                for (int mi = 0; mi < 4; mi++) {
                    uint32_t off = swz64((wm + mi*16 + lrow) * 64 + kb);
                    ldsm4(ah[mi], aAh + off);
                    ldsm4(al[mi], aAl + off);
                }
                uint32_t bh[4][4], bl[4][4];
                #pragma unroll
                for (int nj = 0; nj < 4; nj++) {
                    uint32_t off = swz64((wn + nj*16 + lrow) * 64 + kb);
                    ldsm4(bh[nj], aBh + off);
                    ldsm4(bl[nj], aBl + off);
                }
                // term-major: 32 independent accumulators between reuse
                #pragma unroll
                for (int t = 0; t < 3; t++)
                    #pragma unroll
                    for (int mi = 0; mi < 4; mi++)
                        #pragma unroll
                        for (int ni = 0; ni < 8; ni++) {
                            const int nj = ni >> 1, ns = ni & 1;
                            const uint32_t* a = (t == 2) ? al[mi] : ah[mi];
                            const uint32_t* b = (t == 1) ? bl[nj] : bh[nj];
                            mma16816(acc[mi][ni], a, b[ns], b[ns+2]);
                        }
            }
            if (++stg >= 3) stg = 0;
        }
    }
};

// ---- fused QKV projection: grid (16, 32, 3); z = 0:Q(RoPE) 1:K(RoPE) 2:V ----
__global__ __launch_bounds__(128, 2) void gemm_qkv(
    const __nv_bfloat16* __restrict__ xhi, const __nv_bfloat16* __restrict__ xlo,
    const __nv_bfloat16* __restrict__ whi, const __nv_bfloat16* __restrict__ wlo,
    __nv_bfloat16* __restrict__ qhi, __nv_bfloat16* __restrict__ qlo,
    __nv_bfloat16* __restrict__ khi, __nv_bfloat16* __restrict__ klo,
    __nv_bfloat16* __restrict__ vhi, __nv_bfloat16* __restrict__ vlo)
{
    extern __shared__ char smc[];
    const int z = blockIdx.z;
    const size_t DD = (size_t)D_ * D_;

    GemmCore gc;
    gc.init(smem_u32(smc), blockIdx.x, blockIdx.y);
    gc.Ahi = xhi; gc.Alo = xlo;
    gc.Bhi = whi + z * DD; gc.Blo = wlo + z * DD;

    float acc[4][8][4];
    gc.run(acc);

    __nv_bfloat16* outhi = (z == 0) ? qhi : (z == 1) ? khi : vhi;
    __nv_bfloat16* outlo = (z == 0) ? qlo : (z == 1) ? klo : vlo;
    const bool rope = (z < 2);

    const int rr = gc.lane >> 2;
    const int cp = (gc.lane & 3) * 2;
    #pragma unroll
    for (int mi = 0; mi < 4; mi++) {
        #pragma unroll
        for (int half = 0; half < 2; half++) {
            int m = gc.m0 + gc.wm + mi*16 + rr + half*8;
            int s = m & (S_ - 1);
            #pragma unroll
            for (int ni = 0; ni < 8; ni++) {
                float e = acc[mi][ni][half*2 + 0];
                float o = acc[mi][ni][half*2 + 1];
                int n = gc.n0 + gc.wn + ni*8 + cp;
                if (rope) {
                    int pair = (n & (HD_ - 1)) >> 1;
                    float cc = g_cos[s * F_ + pair], ss = g_sin[s * F_ + pair];
                    float xe = e, xo = o;
                    e = xe * cc - xo * ss;
                    o = xo * cc + xe * ss;
                }
                int br = m >> 11, h = n >> 7, hd = n & (HD_ - 1);
                size_t ei = (((size_t)(br * H_ + h)) * S_ + s) * HD_ + hd;
                __nv_bfloat16 eh = __float2bfloat16(e);
                __nv_bfloat16 oh = __float2bfloat16(o);
                __nv_bfloat16 el = __float2bfloat16(e - __bfloat162float(eh));
                __nv_bfloat16 ol = __float2bfloat16(o - __bfloat162float(oh));
                ((__nv_bfloat162*)outhi)[ei >> 1] = __halves2bfloat162(eh, oh);
                ((__nv_bfloat162*)outlo)[ei >> 1] = __halves2bfloat162(el, ol);
            }
        }
    }
}

// ---- output projection: fp32 row-major [M, 2048] ----
__global__ __launch_bounds__(128, 2) void gemm_out(
    const __nv_bfloat16* __restrict__ Ahi, const __nv_bfloat16* __restrict__ Alo,
    const __nv_bfloat16* __restrict__ Bhi, const __nv_bfloat16* __restrict__ Blo,
    float* __restrict__ outp)
{
    extern __shared__ char smc[];
    GemmCore gc;
    gc.init(smem_u32(smc), blockIdx.x, blockIdx.y);
    gc.Ahi = Ahi; gc.Alo = Alo; gc.Bhi = Bhi; gc.Blo = Blo;

    float acc[4][8][4];
    gc.run(acc);

    const int rr = gc.lane >> 2;
    const int cp = (gc.lane & 3) * 2;
    #pragma unroll
    for (int mi = 0; mi < 4; mi++)
        #pragma unroll
        for (int half = 0; half < 2; half++) {
            int m = gc.m0 + gc.wm + mi*16 + rr + half*8;
            #pragma unroll
            for (int ni = 0; ni < 8; ni++) {
                int n = gc.n0 + gc.wn + ni*8 + cp;
                *(float2*)(outp + (size_t)m * D_ + n) =
                    make_float2(acc[mi][ni][half*2 + 0], acc[mi][ni][half*2 + 1]);
            }
        }
}

// ---------------- flash attention v3: overlapped K/V loads in-place ----------------
// 64-q-row CTAs, 128 threads, 2 CTAs/SM, smem 96 KB (256B rows + swz256).
// K buffer is reloaded for kt+1 right after QK(kt) (hidden under softmax+PV);
// V buffer reloaded after PV(kt) (hidden under next QK+softmax). FIFO wait_group 1.
#define AT2_QH 0         // Q hi: 64 x 256B
#define AT2_QL 16384     // Q lo
#define AT2_KH 32768     // K hi: 64 x 256B
#define AT2_KL 49152     // K lo
#define AT2_VH 65536     // V hi
#define AT2_VL 81920     // V lo
#define A_SMEM 98304

__global__ __launch_bounds__(128, 2) void attn_mma(
    __nv_bfloat16* __restrict__ outhi, __nv_bfloat16* __restrict__ outlo)
{
    extern __shared__ char smc[];
    const uint32_t sb = smem_u32(smc);

    const int tid = threadIdx.x;
    const int lane = tid & 31;
    const int wq = tid >> 5;                                // 0..3
    const int qt = (int)gridDim.x - 1 - (int)blockIdx.x;    // heavy CTAs first
    const int bh = blockIdx.y;
    const size_t base = (size_t)bh * S_ * HD_;
    const float qscale = 0.08838834764831845f;  // 1/sqrt(128)

    // ---- preload Q + K[0] + V[0] (single group) ----
    #pragma unroll
    for (int t = 0; t < 8; t++) {
        int idx = t * 128 + tid;
        int row = idx >> 4, ch = idx & 15;
        size_t go = base + (size_t)(qt * 64 + row) * HD_ + ch * 8;
        uint32_t so = swz256(row * 256 + ch * 16);
        cp16(sb + AT2_QH + so, g_qhi + go);
        cp16(sb + AT2_QL + so, g_qlo + go);
    }
    #pragma unroll
    for (int t = 0; t < 8; t++) {
        int idx = t * 128 + tid;
        int row = idx >> 4, ch = idx & 15;
        size_t go = base + (size_t)row * HD_ + ch * 8;
        uint32_t so = swz256(row * 256 + ch * 16);
        cp16(sb + AT2_KH + so, g_khi + go);
        cp16(sb + AT2_KL + so, g_klo + go);
        cp16(sb + AT2_VH + so, g_vhi + go);
        cp16(sb + AT2_VL + so, g_vlo + go);
    }
    CP_COMMIT();
    asm volatile("cp.async.wait_group 0;" ::: "memory");
    __syncthreads();

    float acc[16][4];
    #pragma unroll
    for (int t8 = 0; t8 < 16; t8++)
        #pragma unroll
        for (int e = 0; e < 4; e++) acc[t8][e] = 0.f;
    float m_run[2] = {-1e30f, -1e30f};
    float l_run[2] = {0.f, 0.f};

    const int r0 = wq * 16 + (lane >> 2);
    const int nkt = qt + 1;
    const int lrow = lane & 15;
    const int lk = (lane >> 4) * 8;

    for (int kt = 0; kt < nkt; kt++) {
        // K(kt) ready: issued in iter kt-1 (or prologue). FIFO: older K group drains first.
        if (kt > 0) {
            asm volatile("cp.async.wait_group 1;" ::: "memory");
            __syncthreads();
        }

        // ---- QK^T (3-term, term-major) ----
        float sacc[8][4];
        #pragma unroll
        for (int ni = 0; ni < 8; ni++)
            #pragma unroll
            for (int e = 0; e < 4; e++) sacc[ni][e] = 0.f;

        #pragma unroll
        for (int kk = 0; kk < 8; kk++) {
            const int kb = (kk * 16 + lk) * 2;
            uint32_t ah[4], al[4];
            uint32_t qo = swz256((wq * 16 + lrow) * 256 + kb);
            ldsm4(ah, sb + AT2_QH + qo);
            ldsm4(al, sb + AT2_QL + qo);
            uint32_t bh4[4][4], bl4[4][4];
            #pragma unroll
            for (int nj = 0; nj < 4; nj++) {
                uint32_t ko = swz256((nj * 16 + lrow) * 256 + kb);
                ldsm4(bh4[nj], sb + AT2_KH + ko);
                ldsm4(bl4[nj], sb + AT2_KL + ko);
            }
            #pragma unroll
            for (int t = 0; t < 3; t++)
                #pragma unroll
                for (int ni = 0; ni < 8; ni++) {
                    const int nj = ni >> 1, ns = ni & 1;
                    const uint32_t* a = (t == 2) ? al : ah;
                    const uint32_t* b = (t == 1) ? bl4[nj] : bh4[nj];
                    mma16816(sacc[ni], a, b[ns], b[ns+2]);
                }
        }

        // K reads complete -> overwrite K buffer with K(kt+1); hides under softmax+PV
        __syncthreads();
        if (kt + 1 < nkt) {
            #pragma unroll
            for (int t = 0; t < 8; t++) {
                int idx = t * 128 + tid;
                int row = idx >> 4, ch = idx & 15;
                size_t go = base + (size_t)((kt + 1) * 64 + row) * HD_ + ch * 8;
                uint32_t so = swz256(row * 256 + ch * 16);
                cp16(sb + AT2_KH + so, g_khi + go);
                cp16(sb + AT2_KL + so, g_klo + go);
            }
        }
        CP_COMMIT();

        // ---- softmax; pack P into bf16 hi/lo A-fragments (registers) ----
        const bool diag = (kt == qt);   // only last tile crosses the causal boundary
        uint32_t phi[8][2], plo[8][2];
        #pragma unroll
        for (int h2 = 0; h2 < 2; h2++) {
            float v[16];
            float mloc = -1e30f;
            if (diag) {
                const int qg = qt * 64 + r0 + h2 * 8;
                #pragma unroll
                for (int ni = 0; ni < 8; ni++)
                    #pragma unroll
                    for (int e = 0; e < 2; e++) {
                        float s = sacc[ni][h2*2 + e] * qscale;
                        int kg = kt * 64 + ni * 8 + (lane & 3) * 2 + e;
                        if (kg > qg) s = -1e30f;
                        v[ni*2 + e] = s;
                        mloc = fmaxf(mloc, s);
                    }
            } else {
                #pragma unroll
                for (int ni = 0; ni < 8; ni++)
                    #pragma unroll
                    for (int e = 0; e < 2; e++) {
                        float s = sacc[ni][h2*2 + e] * qscale;
                        v[ni*2 + e] = s;
                        mloc = fmaxf(mloc, s);
                    }
            }
            mloc = fmaxf(mloc, __shfl_xor_sync(0xffffffffu, mloc, 1));
            mloc = fmaxf(mloc, __shfl_xor_sync(0xffffffffu, mloc, 2));
            float mnew = fmaxf(m_run[h2], mloc);
            float corr = __expf(m_run[h2] - mnew);
            float rsum = 0.f;
            #pragma unroll
            for (int ni = 0; ni < 8; ni++) {
                float p0 = __expf(v[ni*2 + 0] - mnew);
                float p1 = __expf(v[ni*2 + 1] - mnew);
                rsum += p0 + p1;
                __nv_bfloat16 h0 = __float2bfloat16(p0);
                __nv_bfloat16 h1 = __float2bfloat16(p1);
                float l0 = p0 - __bfloat162float(h0);
                float l1 = p1 - __bfloat162float(h1);
                __nv_bfloat162 ph = __halves2bfloat162(h0, h1);
                phi[ni][h2] = *reinterpret_cast<uint32_t*>(&ph);
                plo[ni][h2] = pack_bf16x2(l0, l1);
            }
            rsum += __shfl_xor_sync(0xffffffffu, rsum, 1);
            rsum += __shfl_xor_sync(0xffffffffu, rsum, 2);
            l_run[h2] = l_run[h2] * corr + rsum;
            m_run[h2] = mnew;
            #pragma unroll
            for (int t8 = 0; t8 < 16; t8++) {
                acc[t8][h2*2 + 0] *= corr;
                acc[t8][h2*2 + 1] *= corr;
            }
        }

        // V(kt) ready (issued in iter kt-1 or prologue); K(kt+1) may remain in flight
        asm volatile("cp.async.wait_group 1;" ::: "memory");
        __syncthreads();

        // ---- PV (3-term HMMA), two n16-groups interleaved: reuse distance 4 ----
        #pragma unroll
        for (int kk = 0; kk < 4; kk++) {
            uint32_t aH[4] = { phi[2*kk][0], phi[2*kk][1], phi[2*kk+1][0], phi[2*kk+1][1] };
            uint32_t aL[4] = { plo[2*kk][0], plo[2*kk][1], plo[2*kk+1][0], plo[2*kk+1][1] };
            #pragma unroll
            for (int np = 0; np < 4; np++) {
                const int ng0 = 2*np, ng1 = 2*np + 1;
                uint32_t off0 = swz256((kk * 16 + lrow) * 256 + (ng0 * 16 + lk) * 2);
                uint32_t off1 = swz256((kk * 16 + lrow) * 256 + (ng1 * 16 + lk) * 2);
                uint32_t vh0[4], vl0[4], vh1[4], vl1[4];
                ldsm4t(vh0, sb + AT2_VH + off0);
                ldsm4t(vh1, sb + AT2_VH + off1);
                ldsm4t(vl0, sb + AT2_VL + off0);
                ldsm4t(vl1, sb + AT2_VL + off1);
                const int a0 = 2*ng0, b0v = 2*ng0 + 1, a1 = 2*ng1, b1v = 2*ng1 + 1;
                mma16816(acc[a0],  aH, vh0[0], vh0[1]);
                mma16816(acc[b0v], aH, vh0[2], vh0[3]);
                mma16816(acc[a1],  aH, vh1[0], vh1[1]);
                mma16816(acc[b1v], aH, vh1[2], vh1[3]);
                mma16816(acc[a0],  aL, vh0[0], vh0[1]);
                mma16816(acc[b0v], aL, vh0[2], vh0[3]);
                mma16816(acc[a1],  aL, vh1[0], vh1[1]);
                mma16816(acc[b1v], aL, vh1[2], vh1[3]);
                mma16816(acc[a0],  aH, vl0[0], vl0[1]);
                mma16816(acc[b0v], aH, vl0[2], vl0[3]);
                mma16816(acc[a1],  aH, vl1[0], vl1[1]);
                mma16816(acc[b1v], aH, vl1[2], vl1[3]);
            }
        }

        // V reads complete -> overwrite V buffer with V(kt+1); hides under next QK+softmax
        __syncthreads();
        if (kt + 1 < nkt) {
            #pragma unroll
            for (int t = 0; t < 8; t++) {
                int idx = t * 128 + tid;
                int row = idx >> 4, ch = idx & 15;
                size_t go = base + (size_t)((kt + 1) * 64 + row) * HD_ + ch * 8;
                uint32_t so = swz256(row * 256 + ch * 16);
                cp16(sb + AT2_VH + so, g_vhi + go);
                cp16(sb + AT2_VL + so, g_vlo + go);
            }
        }
        CP_COMMIT();
    }

    // ---- finalize: normalize, split hi/lo, store to [b*s, h*HD+d] ----
    const int b = bh >> 4;
    const int h = bh & 15;
    #pragma unroll
    for (int h2 = 0; h2 < 2; h2++) {
        float inv = 1.0f / l_run[h2];
        int sg = qt * 64 + r0 + h2 * 8;
        size_t rowbase = ((size_t)(b * S_ + sg)) * D_ + h * HD_;
        #pragma unroll
        for (int t8 = 0; t8 < 16; t8++) {
            int col = t8 * 8 + (lane & 3) * 2;
            float e = acc[t8][h2*2 + 0] * inv;
            float o = acc[t8][h2*2 + 1] * inv;
            size_t ei = rowbase + col;
            __nv_bfloat16 eh = __float2bfloat16(e);
            __nv_bfloat16 oh = __float2bfloat16(o);
            __nv_bfloat16 el = __float2bfloat16(e - __bfloat162float(eh));
            __nv_bfloat16 ol = __float2bfloat16(o - __bfloat162float(oh));
            ((__nv_bfloat162*)outhi)[ei >> 1] = __halves2bfloat162(eh, oh);
            ((__nv_bfloat162*)outlo)[ei >> 1] = __halves2bfloat162(el, ol);
        }
    }
}

extern "C" void kernel_launch(void* const* d_in, const int* in_sizes, int n_in,
                              void* d_out, int out_size) {
    (void)in_sizes; (void)n_in; (void)out_size;
    const float* x  = (const float*)d_in[0];
    const float* Wq = (const float*)d_in[1];
    const float* Wk = (const float*)d_in[2];
    const float* Wv = (const float*)d_in[3];
    const float* Wo = (const float*)d_in[4];
    float* out = (float*)d_out;

    __nv_bfloat16 *xhi, *xlo, *whi, *wlo, *qhi, *qlo, *khi, *klo, *vhi, *vlo;
    cudaGetSymbolAddress((void**)&xhi, g_xhi);
    cudaGetSymbolAddress((void**)&xlo, g_xlo);
    cudaGetSymbolAddress((void**)&whi, g_whi);
    cudaGetSymbolAddress((void**)&wlo, g_wlo);
    cudaGetSymbolAddress((void**)&qhi, g_qhi);
    cudaGetSymbolAddress((void**)&qlo, g_qlo);
    cudaGetSymbolAddress((void**)&khi, g_khi);
    cudaGetSymbolAddress((void**)&klo, g_klo);
    cudaGetSymbolAddress((void**)&vhi, g_vhi);
    cudaGetSymbolAddress((void**)&vlo, g_vlo);

    const size_t DD = (size_t)D_ * D_;

    cudaFuncSetAttribute(gemm_qkv, cudaFuncAttributeMaxDynamicSharedMemorySize, GT_SMEM);
    cudaFuncSetAttribute(gemm_out, cudaFuncAttributeMaxDynamicSharedMemorySize, GT_SMEM);
    cudaFuncSetAttribute(attn_mma, cudaFuncAttributeMaxDynamicSharedMemorySize, A_SMEM);

    // launch order: slot 4 = gemm_qkv so the ncu capture window lands on it
    rope_table_kernel<<<(S_*F_ + 255)/256, 256>>>();                                  // 1
    conv_fused<<<dim3(4096, 2), 256>>>(x, Wq, Wk, Wv, Wo, xhi, xlo, whi, wlo, 0);     // 2 (x)
    conv_fused<<<dim3(4096, 4), 256>>>(x, Wq, Wk, Wv, Wo, xhi, xlo, whi, wlo, 2);     // 3 (W)
    gemm_qkv<<<dim3(16, 32, 3), 128, GT_SMEM>>>(xhi, xlo, whi, wlo,
                                                qhi, qlo, khi, klo, vhi, vlo);        // 4
    attn_mma<<<dim3(S_/64, B_*H_), 128, A_SMEM>>>(xhi, xlo);                          // 5
    gemm_out<<<dim3(16, 32), 128, GT_SMEM>>>(xhi, xlo, whi + 3*DD, wlo + 3*DD, out);  // 6
}

// round 17
// speedup vs baseline: 1.1184x; 1.1184x over previous
#include <cuda_runtime.h>
#include <cuda_bf16.h>
#include <cuda_fp16.h>
#include <math.h>
#include <stdint.h>

#define B_  2
#define S_  2048
#define D_  2048
#define H_  16
#define HD_ 128
#define M_  (B_*S_)      // 4096
#define F_  (HD_/2)      // 64

// ---------------- scratch (alloc-free rule: __device__ globals) ----------------
__device__ float g_cos[S_*F_];
__device__ float g_sin[S_*F_];

__device__ __nv_bfloat16 g_qhi[B_*H_*S_*HD_];
__device__ __nv_bfloat16 g_qlo[B_*H_*S_*HD_];
__device__ __nv_bfloat16 g_khi[B_*H_*S_*HD_];
__device__ __nv_bfloat16 g_klo[B_*H_*S_*HD_];
__device__ __half       g_vhi[B_*H_*S_*HD_];   // V split, fp16
__device__ __half       g_vlo[B_*H_*S_*HD_];

__device__ __nv_bfloat16 g_xhi[M_*D_];   // x split; reused as attn-out split
__device__ __nv_bfloat16 g_xlo[M_*D_];
__device__ __half       g_xf16[M_*D_];   // x single fp16 (V-GEMM A operand)
__device__ __nv_bfloat16 g_whi[4*D_*D_]; // slots: 0=Wq 1=Wk 3=Wo (bf16 split)
__device__ __nv_bfloat16 g_wlo[4*D_*D_];
__device__ __half       g_wvh[D_*D_];    // Wv split, fp16
__device__ __half       g_wvl[D_*D_];

// ---------------- PTX helpers (plain sm_100 target: no tcgen05) ----------------
__device__ __forceinline__ uint32_t smem_u32(const void* p) {
    uint32_t a;
    asm("{ .reg .u64 t; cvta.to.shared.u64 t, %1; cvt.u32.u64 %0, t; }" : "=r"(a) : "l"(p));
    return a;
}
__device__ __forceinline__ void cp16(uint32_t s, const void* g) {
    asm volatile("cp.async.cg.shared.global [%0], [%1], 16;" :: "r"(s), "l"(g));
}
#define CP_COMMIT() asm volatile("cp.async.commit_group;")

__device__ __forceinline__ void ldsm4(uint32_t* r, uint32_t addr) {
    asm volatile("ldmatrix.sync.aligned.m8n8.x4.shared.b16 {%0,%1,%2,%3}, [%4];"
        : "=r"(r[0]), "=r"(r[1]), "=r"(r[2]), "=r"(r[3]) : "r"(addr));
}
__device__ __forceinline__ void ldsm4t(uint32_t* r, uint32_t addr) {
    asm volatile("ldmatrix.sync.aligned.m8n8.x4.trans.shared.b16 {%0,%1,%2,%3}, [%4];"
        : "=r"(r[0]), "=r"(r[1]), "=r"(r[2]), "=r"(r[3]) : "r"(addr));
}
__device__ __forceinline__ void mma16816(float* d, const uint32_t* a, uint32_t b0, uint32_t b1) {
    asm volatile(
        "mma.sync.aligned.m16n8k16.row.col.f32.bf16.bf16.f32 "
        "{%0,%1,%2,%3}, {%4,%5,%6,%7}, {%8,%9}, {%0,%1,%2,%3};"
        : "+f"(d[0]), "+f"(d[1]), "+f"(d[2]), "+f"(d[3])
        : "r"(a[0]), "r"(a[1]), "r"(a[2]), "r"(a[3]), "r"(b0), "r"(b1));
}
__device__ __forceinline__ void mma16816h(float* d, const uint32_t* a, uint32_t b0, uint32_t b1) {
    asm volatile(
        "mma.sync.aligned.m16n8k16.row.col.f32.f16.f16.f32 "
        "{%0,%1,%2,%3}, {%4,%5,%6,%7}, {%8,%9}, {%0,%1,%2,%3};"
        : "+f"(d[0]), "+f"(d[1]), "+f"(d[2]), "+f"(d[3])
        : "r"(a[0]), "r"(a[1]), "r"(a[2]), "r"(a[3]), "r"(b0), "r"(b1));
}
// SW64-style bank swizzle for 64B rows; preserves 16B granularity
__device__ __forceinline__ uint32_t swz64(uint32_t x) { return x ^ ((x >> 3) & 0x30); }
// swizzle for 256B rows: row bits [8:10] -> 16B-column bits [4:6]
__device__ __forceinline__ uint32_t swz256(uint32_t x) { return x ^ ((x >> 4) & 0x70); }

// ---------------- RoPE table ----------------
__global__ void rope_table_kernel() {
    int idx = blockIdx.x * blockDim.x + threadIdx.x;
    if (idx >= S_ * F_) return;
    int s = idx >> 6;
    int i = idx & 63;
    double invf = pow(10000.0, -(double)i / 64.0);
    double f = (double)s * invf;
    double sn, cs;
    sincos(f, &sn, &cs);
    g_cos[idx] = (float)cs;
    g_sin[idx] = (float)sn;
}

// ---------------- fp32 -> low-precision splits ----------------
// y: 0,1 = x halves (bf16 hi/lo + fp16 single); 2=Wq 3=Wk (bf16 split, slots 0,1);
// 4=Wv (fp16 split); 5=Wo (bf16 split, slot 3)
__global__ void conv_fused(const float* __restrict__ x,
                           const float* __restrict__ Wq, const float* __restrict__ Wk,
                           const float* __restrict__ Wv, const float* __restrict__ Wo,
                           __nv_bfloat16* __restrict__ xhi, __nv_bfloat16* __restrict__ xlo,
                           __half* __restrict__ xf16,
                           __nv_bfloat16* __restrict__ whi, __nv_bfloat16* __restrict__ wlo,
                           __half* __restrict__ wvh, __half* __restrict__ wvl,
                           int y0)
{
    const int y = blockIdx.y + y0;
    const int i = blockIdx.x * blockDim.x + threadIdx.x;
    const size_t SEG = (size_t)D_ * D_ / 4;

    if (y < 2) {
        float4 v = ((const float4*)(x + (size_t)y * SEG * 4))[i];
        float xs[4] = {v.x, v.y, v.z, v.w};
        size_t off4 = (size_t)y * SEG + i;
        __nv_bfloat16 h[4], l[4];
        #pragma unroll
        for (int j = 0; j < 4; j++) {
            h[j] = __float2bfloat16(xs[j]);
            l[j] = __float2bfloat16(xs[j] - __bfloat162float(h[j]));
        }
        ((__nv_bfloat162*)xhi)[2*off4]   = __halves2bfloat162(h[0], h[1]);
        ((__nv_bfloat162*)xhi)[2*off4+1] = __halves2bfloat162(h[2], h[3]);
        ((__nv_bfloat162*)xlo)[2*off4]   = __halves2bfloat162(l[0], l[1]);
        ((__nv_bfloat162*)xlo)[2*off4+1] = __halves2bfloat162(l[2], l[3]);
        ((__half2*)xf16)[2*off4]   = __floats2half2_rn(xs[0], xs[1]);
        ((__half2*)xf16)[2*off4+1] = __floats2half2_rn(xs[2], xs[3]);
    } else if (y == 4) {
        float4 v = ((const float4*)Wv)[i];
        float xs[4] = {v.x, v.y, v.z, v.w};
        __half h[4], l[4];
        #pragma unroll
        for (int j = 0; j < 4; j++) {
            h[j] = __float2half_rn(xs[j]);
            l[j] = __float2half_rn(xs[j] - __half2float(h[j]));
        }
        ((__half2*)wvh)[2*(size_t)i]   = __halves2half2(h[0], h[1]);
        ((__half2*)wvh)[2*(size_t)i+1] = __halves2half2(h[2], h[3]);
        ((__half2*)wvl)[2*(size_t)i]   = __halves2half2(l[0], l[1]);
        ((__half2*)wvl)[2*(size_t)i+1] = __halves2half2(l[2], l[3]);
    } else {
        const int slot = (y == 5) ? 3 : (y - 2);
        const float* in = (y == 2) ? Wq : (y == 3) ? Wk : Wo;
        float4 v = ((const float4*)in)[i];
        float xs[4] = {v.x, v.y, v.z, v.w};
        size_t off4 = (size_t)slot * SEG + i;
        __nv_bfloat16 h[4], l[4];
        #pragma unroll
        for (int j = 0; j < 4; j++) {
            h[j] = __float2bfloat16(xs[j]);
            l[j] = __float2bfloat16(xs[j] - __bfloat162float(h[j]));
        }
        ((__nv_bfloat162*)whi)[2*off4]   = __halves2bfloat162(h[0], h[1]);
        ((__nv_bfloat162*)whi)[2*off4+1] = __halves2bfloat162(h[2], h[3]);
        ((__nv_bfloat162*)wlo)[2*off4]   = __halves2bfloat162(l[0], l[1]);
        ((__nv_bfloat162*)wlo)[2*off4+1] = __halves2bfloat162(l[2], l[3]);
    }
}

// ---------------- GEMM machinery ----------------
#define KC 32
#define TILE_B (128*64)              // 8192
#define STAGE_B (4*TILE_B)           // 32768
#define GT_SMEM (3*STAGE_B)          // 98304

// 3-term bf16: A split + B split (Q/K/out GEMMs)
struct GemmCore {
    uint32_t sb;
    int tid, lane, wid, wm, wn, m0, n0;
    const __nv_bfloat16 *Ahi, *Alo, *Bhi, *Blo;

    __device__ __forceinline__ void init(uint32_t sb_, int bx, int by) {
        sb = sb_;
        tid = threadIdx.x;
        lane = tid & 31;
        wid = tid >> 5;
        wm = (wid >> 1) * 64;
        wn = (wid & 1) * 64;
        m0 = by * 128;
        n0 = bx * 128;
    }

    __device__ __forceinline__ void load_stage(int stg, int k0) {
        if (k0 < 2048) {
            uint32_t base = sb + stg * STAGE_B;
            #pragma unroll
            for (int t = 0; t < 4; t++) {
                int idx = t * 128 + tid;
                int row = idx >> 2, seg = idx & 3;
                uint32_t so = swz64(row * 64 + seg * 16);
                size_t goA = (size_t)(m0 + row) * D_ + k0 + seg * 8;
                size_t goB = (size_t)(n0 + row) * D_ + k0 + seg * 8;
                cp16(base + 0*TILE_B + so, Ahi + goA);
                cp16(base + 1*TILE_B + so, Alo + goA);
                cp16(base + 2*TILE_B + so, Bhi + goB);
                cp16(base + 3*TILE_B + so, Blo + goB);
            }
        }
        CP_COMMIT();
    }

    __device__ __forceinline__ void run(float acc[4][8][4]) {
        #pragma unroll
        for (int mi = 0; mi < 4; mi++)
            #pragma unroll
            for (int ni = 0; ni < 8; ni++)
                #pragma unroll
                for (int e = 0; e < 4; e++) acc[mi][ni][e] = 0.f;

        load_stage(0, 0);
        load_stage(1, KC);
        const int NCH = 2048 / KC;
        const int lrow = lane & 15;
        const int lk   = (lane >> 4) * 8;

        int stg = 0;
        for (int c = 0; c < NCH; c++) {
            asm volatile("cp.async.wait_group 1;" ::: "memory");
            __syncthreads();
            int nst = stg + 2; if (nst >= 3) nst -= 3;
            load_stage(nst, (c + 2) * KC);

            const uint32_t st = sb + stg * STAGE_B;
            const uint32_t aAh = st, aAl = st + TILE_B, aBh = st + 2*TILE_B, aBl = st + 3*TILE_B;

            #pragma unroll
            for (int kk = 0; kk < 2; kk++) {
                const int kb = (kk * 16 + lk) * 2;
                uint32_t ah[4][4], al[4][4];
                #pragma unroll
                for (int mi = 0; mi < 4; mi++) {
                    uint32_t off = swz64((wm + mi*16 + lrow) * 64 + kb);
                    ldsm4(ah[mi], aAh + off);
                    ldsm4(al[mi], aAl + off);
                }
                uint32_t bh[4][4], bl[4][4];
                #pragma unroll
                for (int nj = 0; nj < 4; nj++) {
                    uint32_t off = swz64((wn + nj*16 + lrow) * 64 + kb);
                    ldsm4(bh[nj], aBh + off);
                    ldsm4(bl[nj], aBl + off);
                }
                #pragma unroll
                for (int t = 0; t < 3; t++)
                    #pragma unroll
                    for (int mi = 0; mi < 4; mi++)
                        #pragma unroll
                        for (int ni = 0; ni < 8; ni++) {
                            const int nj = ni >> 1, ns = ni & 1;
                            const uint32_t* a = (t == 2) ? al[mi] : ah[mi];
                            const uint32_t* b = (t == 1) ? bl[nj] : bh[nj];
                            mma16816(acc[mi][ni], a, b[ns], b[ns+2]);
                        }
            }
            if (++stg >= 3) stg = 0;
        }
    }
};

// 2-term fp16: A single + B split (V GEMM). Stage: A 8K | Bh 8K | Bl 8K.
struct GemmCoreV {
    uint32_t sb;
    int tid, lane, wid, wm, wn, m0, n0;
    const __half *A, *Bh, *Bl;

    __device__ __forceinline__ void init(uint32_t sb_, int bx, int by) {
        sb = sb_;
        tid = threadIdx.x;
        lane = tid & 31;
        wid = tid >> 5;
        wm = (wid >> 1) * 64;
        wn = (wid & 1) * 64;
        m0 = by * 128;
        n0 = bx * 128;
    }

    __device__ __forceinline__ void load_stage(int stg, int k0) {
        if (k0 < 2048) {
            uint32_t base = sb + stg * STAGE_B;
            #pragma unroll
            for (int t = 0; t < 4; t++) {
                int idx = t * 128 + tid;
                int row = idx >> 2, seg = idx & 3;
                uint32_t so = swz64(row * 64 + seg * 16);
                size_t goA = (size_t)(m0 + row) * D_ + k0 + seg * 8;
                size_t goB = (size_t)(n0 + row) * D_ + k0 + seg * 8;
                cp16(base + 0*TILE_B + so, A  + goA);
                cp16(base + 1*TILE_B + so, Bh + goB);
                cp16(base + 2*TILE_B + so, Bl + goB);
            }
        }
        CP_COMMIT();
    }

    __device__ __forceinline__ void run(float acc[4][8][4]) {
        #pragma unroll
        for (int mi = 0; mi < 4; mi++)
            #pragma unroll
            for (int ni = 0; ni < 8; ni++)
                #pragma unroll
                for (int e = 0; e < 4; e++) acc[mi][ni][e] = 0.f;

        load_stage(0, 0);
        load_stage(1, KC);
        const int NCH = 2048 / KC;
        const int lrow = lane & 15;
        const int lk   = (lane >> 4) * 8;

        int stg = 0;
        for (int c = 0; c < NCH; c++) {
            asm volatile("cp.async.wait_group 1;" ::: "memory");
            __syncthreads();
            int nst = stg + 2; if (nst >= 3) nst -= 3;
            load_stage(nst, (c + 2) * KC);

            const uint32_t st = sb + stg * STAGE_B;
            const uint32_t aA = st, aBh = st + TILE_B, aBl = st + 2*TILE_B;

            #pragma unroll
            for (int kk = 0; kk < 2; kk++) {
                const int kb = (kk * 16 + lk) * 2;
                uint32_t af[4][4];
                #pragma unroll
                for (int mi = 0; mi < 4; mi++) {
                    uint32_t off = swz64((wm + mi*16 + lrow) * 64 + kb);
                    ldsm4(af[mi], aA + off);
                }
                uint32_t bh[4][4], bl[4][4];
                #pragma unroll
                for (int nj = 0; nj < 4; nj++) {
                    uint32_t off = swz64((wn + nj*16 + lrow) * 64 + kb);
                    ldsm4(bh[nj], aBh + off);
                    ldsm4(bl[nj], aBl + off);
                }
                #pragma unroll
                for (int t = 0; t < 2; t++)
                    #pragma unroll
                    for (int mi = 0; mi < 4; mi++)
                        #pragma unroll
                        for (int ni = 0; ni < 8; ni++) {
                            const int nj = ni >> 1, ns = ni & 1;
                            const uint32_t* b = (t == 1) ? bl[nj] : bh[nj];
                            mma16816h(acc[mi][ni], af[mi], b[ns], b[ns+2]);
                        }
            }
            if (++stg >= 3) stg = 0;
        }
    }
};

// ---- fused QKV projection: grid (16, 32, 3); z = 0:Q(RoPE,bf16x3) 1:K(RoPE,bf16x3) 2:V(fp16x2) ----
__global__ __launch_bounds__(128, 2) void gemm_qkv(
    const __nv_bfloat16* __restrict__ xhi, const __nv_bfloat16* __restrict__ xlo,
    const __half* __restrict__ xf16,
    const __nv_bfloat16* __restrict__ whi, const __nv_bfloat16* __restrict__ wlo,
    const __half* __restrict__ wvh, const __half* __restrict__ wvl,
    __nv_bfloat16* __restrict__ qhi, __nv_bfloat16* __restrict__ qlo,
    __nv_bfloat16* __restrict__ khi, __nv_bfloat16* __restrict__ klo,
    __half* __restrict__ vhi, __half* __restrict__ vlo)
{
    extern __shared__ char smc[];
    const int z = blockIdx.z;
    const size_t DD = (size_t)D_ * D_;

    float acc[4][8][4];
    int lane_, wm_, wn_, m0_, n0_;

    if (z == 2) {
        GemmCoreV gc;
        gc.init(smem_u32(smc), blockIdx.x, blockIdx.y);
        gc.A = xf16; gc.Bh = wvh; gc.Bl = wvl;
        gc.run(acc);
        lane_ = gc.lane; wm_ = gc.wm; wn_ = gc.wn; m0_ = gc.m0; n0_ = gc.n0;

        const int rr = lane_ >> 2;
        const int cp = (lane_ & 3) * 2;
        #pragma unroll
        for (int mi = 0; mi < 4; mi++)
            #pragma unroll
            for (int half = 0; half < 2; half++) {
                int m = m0_ + wm_ + mi*16 + rr + half*8;
                int s = m & (S_ - 1);
                #pragma unroll
                for (int ni = 0; ni < 8; ni++) {
                    float e = acc[mi][ni][half*2 + 0];
                    float o = acc[mi][ni][half*2 + 1];
                    int n = n0_ + wn_ + ni*8 + cp;
                    int br = m >> 11, h = n >> 7, hd = n & (HD_ - 1);
                    size_t ei = (((size_t)(br * H_ + h)) * S_ + s) * HD_ + hd;
                    __half eh = __float2half_rn(e);
                    __half oh = __float2half_rn(o);
                    __half el = __float2half_rn(e - __half2float(eh));
                    __half ol = __float2half_rn(o - __half2float(oh));
                    ((__half2*)vhi)[ei >> 1] = __halves2half2(eh, oh);
                    ((__half2*)vlo)[ei >> 1] = __halves2half2(el, ol);
                }
            }
        return;
    }

    GemmCore gc;
    gc.init(smem_u32(smc), blockIdx.x, blockIdx.y);
    gc.Ahi = xhi; gc.Alo = xlo;
    gc.Bhi = whi + z * DD; gc.Blo = wlo + z * DD;
    gc.run(acc);
    lane_ = gc.lane; wm_ = gc.wm; wn_ = gc.wn; m0_ = gc.m0; n0_ = gc.n0;

    __nv_bfloat16* outhi = (z == 0) ? qhi : khi;
    __nv_bfloat16* outlo = (z == 0) ? qlo : klo;

    const int rr = lane_ >> 2;
    const int cp = (lane_ & 3) * 2;
    #pragma unroll
    for (int mi = 0; mi < 4; mi++) {
        #pragma unroll
        for (int half = 0; half < 2; half++) {
            int m = m0_ + wm_ + mi*16 + rr + half*8;
            int s = m & (S_ - 1);
            #pragma unroll
            for (int ni = 0; ni < 8; ni++) {
                float e = acc[mi][ni][half*2 + 0];
                float o = acc[mi][ni][half*2 + 1];
                int n = n0_ + wn_ + ni*8 + cp;
                int pair = (n & (HD_ - 1)) >> 1;
                float cc = g_cos[s * F_ + pair], ss = g_sin[s * F_ + pair];
                float xe = e, xo = o;
                e = xe * cc - xo * ss;
                o = xo * cc + xe * ss;
                int br = m >> 11, h = n >> 7, hd = n & (HD_ - 1);
                size_t ei = (((size_t)(br * H_ + h)) * S_ + s) * HD_ + hd;
                __nv_bfloat16 eh = __float2bfloat16(e);
                __nv_bfloat16 oh = __float2bfloat16(o);
                __nv_bfloat16 el = __float2bfloat16(e - __bfloat162float(eh));
                __nv_bfloat16 ol = __float2bfloat16(o - __bfloat162float(oh));
                ((__nv_bfloat162*)outhi)[ei >> 1] = __halves2bfloat162(eh, oh);
                ((__nv_bfloat162*)outlo)[ei >> 1] = __halves2bfloat162(el, ol);
            }
        }
    }
}

// ---- output projection: fp32 row-major [M, 2048] (3-term bf16) ----
__global__ __launch_bounds__(128, 2) void gemm_out(
    const __nv_bfloat16* __restrict__ Ahi, const __nv_bfloat16* __restrict__ Alo,
    const __nv_bfloat16* __restrict__ Bhi, const __nv_bfloat16* __restrict__ Blo,
    float* __restrict__ outp)
{
    extern __shared__ char smc[];
    GemmCore gc;
    gc.init(smem_u32(smc), blockIdx.x, blockIdx.y);
    gc.Ahi = Ahi; gc.Alo = Alo; gc.Bhi = Bhi; gc.Blo = Blo;

    float acc[4][8][4];
    gc.run(acc);

    const int rr = gc.lane >> 2;
    const int cp = (gc.lane & 3) * 2;
    #pragma unroll
    for (int mi = 0; mi < 4; mi++)
        #pragma unroll
        for (int half = 0; half < 2; half++) {
            int m = gc.m0 + gc.wm + mi*16 + rr + half*8;
            #pragma unroll
            for (int ni = 0; ni < 8; ni++) {
                int n = gc.n0 + gc.wn + ni*8 + cp;
                *(float2*)(outp + (size_t)m * D_ + n) =
                    make_float2(acc[mi][ni][half*2 + 0], acc[mi][ni][half*2 + 1]);
            }
        }
}

// ---------------- flash attention: bf16 3-term QK^T + fp16 2-term PV ----------------
// 64-q-row CTAs, 128 threads, 2 CTAs/SM, smem 96 KB (256B rows + swz256).
// K reloaded in-place after QK (hidden under softmax+PV); V reloaded after PV.
#define AT2_QH 0         // Q hi: 64 x 256B
#define AT2_QL 16384     // Q lo
#define AT2_KH 32768     // K hi: 64 x 256B
#define AT2_KL 49152     // K lo
#define AT2_VH 65536     // V hi (fp16)
#define AT2_VL 81920     // V lo (fp16)
#define A_SMEM 98304

__global__ __launch_bounds__(128, 2) void attn_mma(
    __nv_bfloat16* __restrict__ outhi, __nv_bfloat16* __restrict__ outlo)
{
    extern __shared__ char smc[];
    const uint32_t sb = smem_u32(smc);

    const int tid = threadIdx.x;
    const int lane = tid & 31;
    const int wq = tid >> 5;                                // 0..3
    const int qt = (int)gridDim.x - 1 - (int)blockIdx.x;    // heavy CTAs first
    const int bh = blockIdx.y;
    const size_t base = (size_t)bh * S_ * HD_;
    const float qscale = 0.08838834764831845f;  // 1/sqrt(128)

    // ---- preload Q + K[0] + V[0] (single group) ----
    #pragma unroll
    for (int t = 0; t < 8; t++) {
        int idx = t * 128 + tid;
        int row = idx >> 4, ch = idx & 15;
        size_t go = base + (size_t)(qt * 64 + row) * HD_ + ch * 8;
        uint32_t so = swz256(row * 256 + ch * 16);
        cp16(sb + AT2_QH + so, g_qhi + go);
        cp16(sb + AT2_QL + so, g_qlo + go);
    }
    #pragma unroll
    for (int t = 0; t < 8; t++) {
        int idx = t * 128 + tid;
        int row = idx >> 4, ch = idx & 15;
        size_t go = base + (size_t)row * HD_ + ch * 8;
        uint32_t so = swz256(row * 256 + ch * 16);
        cp16(sb + AT2_KH + so, g_khi + go);
        cp16(sb + AT2_KL + so, g_klo + go);
        cp16(sb + AT2_VH + so, g_vhi + go);
        cp16(sb + AT2_VL + so, g_vlo + go);
    }
    CP_COMMIT();
    asm volatile("cp.async.wait_group 0;" ::: "memory");
    __syncthreads();

    float acc[16][4];
    #pragma unroll
    for (int t8 = 0; t8 < 16; t8++)
        #pragma unroll
        for (int e = 0; e < 4; e++) acc[t8][e] = 0.f;
    float m_run[2] = {-1e30f, -1e30f};
    float l_run[2] = {0.f, 0.f};

    const int r0 = wq * 16 + (lane >> 2);
    const int nkt = qt + 1;
    const int lrow = lane & 15;
    const int lk = (lane >> 4) * 8;

    for (int kt = 0; kt < nkt; kt++) {
        if (kt > 0) {
            asm volatile("cp.async.wait_group 1;" ::: "memory");
            __syncthreads();
        }

        // ---- QK^T (3-term bf16, term-major) ----
        float sacc[8][4];
        #pragma unroll
        for (int ni = 0; ni < 8; ni++)
            #pragma unroll
            for (int e = 0; e < 4; e++) sacc[ni][e] = 0.f;

        #pragma unroll
        for (int kk = 0; kk < 8; kk++) {
            const int kb = (kk * 16 + lk) * 2;
            uint32_t ah[4], al[4];
            uint32_t qo = swz256((wq * 16 + lrow) * 256 + kb);
            ldsm4(ah, sb + AT2_QH + qo);
            ldsm4(al, sb + AT2_QL + qo);
            uint32_t bh4[4][4], bl4[4][4];
            #pragma unroll
            for (int nj = 0; nj < 4; nj++) {
                uint32_t ko = swz256((nj * 16 + lrow) * 256 + kb);
                ldsm4(bh4[nj], sb + AT2_KH + ko);
                ldsm4(bl4[nj], sb + AT2_KL + ko);
            }
            #pragma unroll
            for (int t = 0; t < 3; t++)
                #pragma unroll
                for (int ni = 0; ni < 8; ni++) {
                    const int nj = ni >> 1, ns = ni & 1;
                    const uint32_t* a = (t == 2) ? al : ah;
                    const uint32_t* b = (t == 1) ? bl4[nj] : bh4[nj];
                    mma16816(sacc[ni], a, b[ns], b[ns+2]);
                }
        }

        // K reads complete -> overwrite K buffer with K(kt+1); hides under softmax+PV
        __syncthreads();
        if (kt + 1 < nkt) {
            #pragma unroll
            for (int t = 0; t < 8; t++) {
                int idx = t * 128 + tid;
                int row = idx >> 4, ch = idx & 15;
                size_t go = base + (size_t)((kt + 1) * 64 + row) * HD_ + ch * 8;
                uint32_t so = swz256(row * 256 + ch * 16);
                cp16(sb + AT2_KH + so, g_khi + go);
                cp16(sb + AT2_KL + so, g_klo + go);
            }
        }
        CP_COMMIT();

        // ---- softmax; pack P as single fp16 A-fragments (registers) ----
        const bool diag = (kt == qt);
        uint32_t phi[8][2];
        #pragma unroll
        for (int h2 = 0; h2 < 2; h2++) {
            float v[16];
            float mloc = -1e30f;
            if (diag) {
                const int qg = qt * 64 + r0 + h2 * 8;
                #pragma unroll
                for (int ni = 0; ni < 8; ni++)
                    #pragma unroll
                    for (int e = 0; e < 2; e++) {
                        float s = sacc[ni][h2*2 + e] * qscale;
                        int kg = kt * 64 + ni * 8 + (lane & 3) * 2 + e;
                        if (kg > qg) s = -1e30f;
                        v[ni*2 + e] = s;
                        mloc = fmaxf(mloc, s);
                    }
            } else {
                #pragma unroll
                for (int ni = 0; ni < 8; ni++)
                    #pragma unroll
                    for (int e = 0; e < 2; e++) {
                        float s = sacc[ni][h2*2 + e] * qscale;
                        v[ni*2 + e] = s;
                        mloc = fmaxf(mloc, s);
                    }
            }
            mloc = fmaxf(mloc, __shfl_xor_sync(0xffffffffu, mloc, 1));
            mloc = fmaxf(mloc, __shfl_xor_sync(0xffffffffu, mloc, 2));
            float mnew = fmaxf(m_run[h2], mloc);
            float corr = __expf(m_run[h2] - mnew);
            float rsum = 0.f;
            #pragma unroll
            for (int ni = 0; ni < 8; ni++) {
                float p0 = __expf(v[ni*2 + 0] - mnew);
                float p1 = __expf(v[ni*2 + 1] - mnew);
                rsum += p0 + p1;
                __half2 ph = __floats2half2_rn(p0, p1);
                phi[ni][h2] = *reinterpret_cast<uint32_t*>(&ph);
            }
            rsum += __shfl_xor_sync(0xffffffffu, rsum, 1);
            rsum += __shfl_xor_sync(0xffffffffu, rsum, 2);
            l_run[h2] = l_run[h2] * corr + rsum;
            m_run[h2] = mnew;
            #pragma unroll
            for (int t8 = 0; t8 < 16; t8++) {
                acc[t8][h2*2 + 0] *= corr;
                acc[t8][h2*2 + 1] *= corr;
            }
        }

        // V(kt) ready; K(kt+1) may remain in flight
        asm volatile("cp.async.wait_group 1;" ::: "memory");
        __syncthreads();

        // ---- PV (2-term fp16): P single x (Vh + Vl) ----
        #pragma unroll
        for (int kk = 0; kk < 4; kk++) {
            uint32_t aH[4] = { phi[2*kk][0], phi[2*kk][1], phi[2*kk+1][0], phi[2*kk+1][1] };
            #pragma unroll
            for (int np = 0; np < 4; np++) {
                const int ng0 = 2*np, ng1 = 2*np + 1;
                uint32_t off0 = swz256((kk * 16 + lrow) * 256 + (ng0 * 16 + lk) * 2);
                uint32_t off1 = swz256((kk * 16 + lrow) * 256 + (ng1 * 16 + lk) * 2);
                uint32_t vh0[4], vl0[4], vh1[4], vl1[4];
                ldsm4t(vh0, sb + AT2_VH + off0);
                ldsm4t(vh1, sb + AT2_VH + off1);
                ldsm4t(vl0, sb + AT2_VL + off0);
                ldsm4t(vl1, sb + AT2_VL + off1);
                const int a0 = 2*ng0, b0v = 2*ng0 + 1, a1 = 2*ng1, b1v = 2*ng1 + 1;
                mma16816h(acc[a0],  aH, vh0[0], vh0[1]);
                mma16816h(acc[b0v], aH, vh0[2], vh0[3]);
                mma16816h(acc[a1],  aH, vh1[0], vh1[1]);
                mma16816h(acc[b1v], aH, vh1[2], vh1[3]);
                mma16816h(acc[a0],  aH, vl0[0], vl0[1]);
                mma16816h(acc[b0v], aH, vl0[2], vl0[3]);
                mma16816h(acc[a1],  aH, vl1[0], vl1[1]);
                mma16816h(acc[b1v], aH, vl1[2], vl1[3]);
            }
        }

        // V reads complete -> overwrite V buffer with V(kt+1)
        __syncthreads();
        if (kt + 1 < nkt) {
            #pragma unroll
            for (int t = 0; t < 8; t++) {
                int idx = t * 128 + tid;
                int row = idx >> 4, ch = idx & 15;
                size_t go = base + (size_t)((kt + 1) * 64 + row) * HD_ + ch * 8;
                uint32_t so = swz256(row * 256 + ch * 16);
                cp16(sb + AT2_VH + so, g_vhi + go);
                cp16(sb + AT2_VL + so, g_vlo + go);
            }
        }
        CP_COMMIT();
    }

    // ---- finalize: normalize, split hi/lo (bf16 for out-GEMM), store ----
    const int b = bh >> 4;
    const int h = bh & 15;
    #pragma unroll
    for (int h2 = 0; h2 < 2; h2++) {
        float inv = 1.0f / l_run[h2];
        int sg = qt * 64 + r0 + h2 * 8;
        size_t rowbase = ((size_t)(b * S_ + sg)) * D_ + h * HD_;
        #pragma unroll
        for (int t8 = 0; t8 < 16; t8++) {
            int col = t8 * 8 + (lane & 3) * 2;
            float e = acc[t8][h2*2 + 0] * inv;
            float o = acc[t8][h2*2 + 1] * inv;
            size_t ei = rowbase + col;
            __nv_bfloat16 eh = __float2bfloat16(e);
            __nv_bfloat16 oh = __float2bfloat16(o);
            __nv_bfloat16 el = __float2bfloat16(e - __bfloat162float(eh));
            __nv_bfloat16 ol = __float2bfloat16(o - __bfloat162float(oh));
            ((__nv_bfloat162*)outhi)[ei >> 1] = __halves2bfloat162(eh, oh);
            ((__nv_bfloat162*)outlo)[ei >> 1] = __halves2bfloat162(el, ol);
        }
    }
}

extern "C" void kernel_launch(void* const* d_in, const int* in_sizes, int n_in,
                              void* d_out, int out_size) {
    (void)in_sizes; (void)n_in; (void)out_size;
    const float* x  = (const float*)d_in[0];
    const float* Wq = (const float*)d_in[1];
    const float* Wk = (const float*)d_in[2];
    const float* Wv = (const float*)d_in[3];
    const float* Wo = (const float*)d_in[4];
    float* out = (float*)d_out;

    __nv_bfloat16 *xhi, *xlo, *whi, *wlo, *qhi, *qlo, *khi, *klo;
    __half *xf16, *wvh, *wvl, *vhi, *vlo;
    cudaGetSymbolAddress((void**)&xhi, g_xhi);
    cudaGetSymbolAddress((void**)&xlo, g_xlo);
    cudaGetSymbolAddress((void**)&xf16, g_xf16);
    cudaGetSymbolAddress((void**)&whi, g_whi);
    cudaGetSymbolAddress((void**)&wlo, g_wlo);
    cudaGetSymbolAddress((void**)&wvh, g_wvh);
    cudaGetSymbolAddress((void**)&wvl, g_wvl);
    cudaGetSymbolAddress((void**)&qhi, g_qhi);
    cudaGetSymbolAddress((void**)&qlo, g_qlo);
    cudaGetSymbolAddress((void**)&khi, g_khi);
    cudaGetSymbolAddress((void**)&klo, g_klo);
    cudaGetSymbolAddress((void**)&vhi, g_vhi);
    cudaGetSymbolAddress((void**)&vlo, g_vlo);

    const size_t DD = (size_t)D_ * D_;

    cudaFuncSetAttribute(gemm_qkv, cudaFuncAttributeMaxDynamicSharedMemorySize, GT_SMEM);
    cudaFuncSetAttribute(gemm_out, cudaFuncAttributeMaxDynamicSharedMemorySize, GT_SMEM);
    cudaFuncSetAttribute(attn_mma, cudaFuncAttributeMaxDynamicSharedMemorySize, A_SMEM);

    rope_table_kernel<<<(S_*F_ + 255)/256, 256>>>();
    conv_fused<<<dim3(4096, 2), 256>>>(x, Wq, Wk, Wv, Wo, xhi, xlo, xf16, whi, wlo, wvh, wvl, 0);
    conv_fused<<<dim3(4096, 4), 256>>>(x, Wq, Wk, Wv, Wo, xhi, xlo, xf16, whi, wlo, wvh, wvl, 2);
    gemm_qkv<<<dim3(16, 32, 3), 128, GT_SMEM>>>(xhi, xlo, xf16, whi, wlo, wvh, wvl,
                                                qhi, qlo, khi, klo, vhi, vlo);
    attn_mma<<<dim3(S_/64, B_*H_), 128, A_SMEM>>>(xhi, xlo);
    gemm_out<<<dim3(16, 32), 128, GT_SMEM>>>(xhi, xlo, whi + 3*DD, wlo + 3*DD, out);
}